// round 15
// baseline (speedup 1.0000x reference)
#include <cuda_runtime.h>
#include <math.h>
#include <stdint.h>

#define DM     2048
#define DIN    4096
#define NH     32
#define DH     128
#define DS     64
#define NC     16
#define CHK    256
#define CONVD  4224
#define DPROJ  8352
#define BATCH  2
#define SEQ    4096
#define BL     (BATCH*SEQ)

// ---------------- scratch (device globals; no allocations allowed) ----------
__device__ __align__(1024) float g_z[BL*DIN];
__device__ __align__(1024) float g_xbc[BL*CONVD];
__device__ __align__(1024) float g_dtraw[BL*NH];
__device__ __align__(1024) float g_x[BL*DIN];
__device__ __align__(1024) float g_Bc[BL*DS];
__device__ __align__(1024) float g_Cc[BL*DS];
__device__ float g_dt[BL*NH];
__device__ float g_r[BATCH*NC*NH*CHK];
__device__ float g_ecum[BATCH*NC*NH*CHK];
__device__ float g_cdecay[BATCH*NC*NH];
__device__ float g_GT[BATCH*NC*CHK*CHK];
__device__ float g_states[BATCH*NC*NH*DH*DS];
__device__ float g_prev[BATCH*NC*NH*DH*DS];
__device__ __align__(1024) float g_y[BL*DIN];
// tf32-rounded GEMM inputs
__device__ __align__(1024) float g_u[BL*DM];
__device__ __align__(1024) float g_Win[DPROJ*DM];
__device__ __align__(1024) float g_Wout[DM*DIN];

__device__ __forceinline__ float rna_tf32(float x) {
    float y;
    asm("cvt.rna.tf32.f32 %0, %1;" : "=f"(y) : "f"(x));
    return y;
}

// silu with 1 MUFU (EX2) + FMA-pipe reciprocal (bit trick + 3 Newton, ~1e-7)
__device__ __forceinline__ float silu_fast(float x) {
    float e = __expf(-x);
    e = fminf(e, 1e30f);                 // keep d finite for the bit trick
    float d = 1.f + e;
    float r = __uint_as_float(0x7EF311C3u - __float_as_uint(d));
    r = r * (2.f - d * r);
    r = r * (2.f - d * r);
    r = r * (2.f - d * r);
    return x * r;
}

// ---------------- merged prep: round u / W_in / W_out to tf32 (rna) ---------
#define N4_U    (BL*DM/4)
#define N4_WIN  (DPROJ*DM/4)
#define N4_WOUT (DM*DIN/4)
__global__ __launch_bounds__(256)
void prep_round_all(const float* __restrict__ u,
                    const float* __restrict__ W_in,
                    const float* __restrict__ W_out) {
    int i = blockIdx.x * 256 + threadIdx.x;
    const float* src; float* dst; int off;
    if (i < N4_U)                     { src = u;     dst = g_u;    off = i; }
    else if (i < N4_U + N4_WIN)       { src = W_in;  dst = g_Win;  off = i - N4_U; }
    else if (i < N4_U + N4_WIN + N4_WOUT) { src = W_out; dst = g_Wout; off = i - N4_U - N4_WIN; }
    else return;
    float4 v = reinterpret_cast<const float4*>(src)[off];
    v.x = rna_tf32(v.x); v.y = rna_tf32(v.y);
    v.z = rna_tf32(v.z); v.w = rna_tf32(v.w);
    reinterpret_cast<float4*>(dst)[off] = v;
}

// ======================= mma.sync tf32 GEMM (R11 flat loop, untouched) ======
#define BM 128
#define BN 128
#define BK 32
#define GSTG 3
#define A_STG_F (BM*BK)
#define B_STG_F (BN*BK)
#define GSMEM_BYTES (GSTG*(A_STG_F+B_STG_F)*4)   // 98304

__device__ __forceinline__ uint32_t smem_u32(const void* p) {
    uint32_t a;
    asm("{ .reg .u64 t; cvta.to.shared.u64 t, %1; cvt.u32.u64 %0, t; }"
        : "=r"(a) : "l"(p));
    return a;
}
__device__ __forceinline__ void cp_async16(uint32_t dst, const void* src, int srcsize) {
    asm volatile("cp.async.cg.shared.global [%0], [%1], 16, %2;"
                 :: "r"(dst), "l"(src), "r"(srcsize) : "memory");
}
#define CP_COMMIT() asm volatile("cp.async.commit_group;" ::: "memory")
#define CP_WAIT1()  asm volatile("cp.async.wait_group 1;" ::: "memory")

#define LDSM4(r0, r1, r2, r3, addr) \
    asm volatile("ldmatrix.sync.aligned.m8n8.x4.shared.b16 {%0,%1,%2,%3}, [%4];" \
        : "=r"(r0), "=r"(r1), "=r"(r2), "=r"(r3) : "r"(addr))

__device__ __forceinline__ void mma_tf32(float* c, const uint32_t* a, const uint32_t* b) {
    asm volatile(
        "mma.sync.aligned.m16n8k8.row.col.f32.tf32.tf32.f32 "
        "{%0,%1,%2,%3}, {%4,%5,%6,%7}, {%8,%9}, {%0,%1,%2,%3};"
        : "+f"(c[0]), "+f"(c[1]), "+f"(c[2]), "+f"(c[3])
        : "r"(a[0]), "r"(a[1]), "r"(a[2]), "r"(a[3]), "r"(b[0]), "r"(b[1]));
}

// MODE 0: in-proj -> scatter into g_z / g_xbc / g_dtraw
// MODE 1: plain store to Cout with row stride N
template<int MODE>
__global__ __launch_bounds__(256, 2)
void gemm_mma(const float* __restrict__ A, const float* __restrict__ Bw,
              float* __restrict__ Cout, int N, int K) {
    extern __shared__ __align__(128) float smem[];
    const uint32_t aAddr0 = smem_u32(smem);
    const uint32_t bAddr0 = aAddr0 + GSTG * A_STG_F * 4;

    const int tid  = threadIdx.x;
    const int wid  = tid >> 5;
    const int lane = tid & 31;
    const int m0 = blockIdx.y * BM;
    const int n0 = blockIdx.x * BN;
    const int wm = (wid >> 2) * 64;
    const int wn = (wid & 3) * 32;
    const int nk = K / BK;

    float acc[4][4][4];
#pragma unroll
    for (int i = 0; i < 4; i++)
#pragma unroll
        for (int j = 0; j < 4; j++)
#pragma unroll
            for (int q = 0; q < 4; q++) acc[i][j][q] = 0.f;

    const int t4 = lane >> 3;
    const int rowA = wm + ((t4 & 1) << 3) + (lane & 7);
    const int halfA = t4 >> 1;
    const int rowB = wn + ((t4 >> 1) << 3) + (lane & 7);
    const int halfB = t4 & 1;

    auto issue_loads = [&](int stage, int kiter) {
        const float* Ag = A + (size_t)m0 * K + kiter * BK;
        uint32_t aS = aAddr0 + stage * A_STG_F * 4;
#pragma unroll
        for (int i = 0; i < 4; i++) {
            int lin = i * 256 + tid;
            int row = lin >> 3, c = lin & 7;
            uint32_t dst = aS + (row * BK + ((c ^ (row & 7)) << 2)) * 4;
            cp_async16(dst, Ag + (size_t)row * K + c * 4, 16);
        }
        const float* Bg = Bw + (size_t)kiter * BK;
        uint32_t bS = bAddr0 + stage * B_STG_F * 4;
#pragma unroll
        for (int i = 0; i < 4; i++) {
            int lin = i * 256 + tid;
            int row = lin >> 3, c = lin & 7;
            int gr = n0 + row;
            int ok = (gr < N) ? 16 : 0;
            uint32_t dst = bS + (row * BK + ((c ^ (row & 7)) << 2)) * 4;
            cp_async16(dst, Bg + (size_t)(ok ? gr : 0) * K + c * 4, ok);
        }
    };

    issue_loads(0, 0); CP_COMMIT();
    issue_loads(1, 1); CP_COMMIT();

    for (int i = 0; i < nk; i++) {
        CP_WAIT1();
        __syncthreads();
        int nxt = i + 2;
        if (nxt < nk) issue_loads(nxt % GSTG, nxt);
        CP_COMMIT();

        int st = i % GSTG;
        uint32_t aS = aAddr0 + st * A_STG_F * 4;
        uint32_t bS = bAddr0 + st * B_STG_F * 4;
#pragma unroll
        for (int ks = 0; ks < 4; ks++) {
            uint32_t a[4][4];
            uint32_t offA = rowA * (BK * 4) + ((((ks << 1) + halfA) ^ (rowA & 7)) << 4);
#pragma unroll
            for (int mf = 0; mf < 4; mf++)
                LDSM4(a[mf][0], a[mf][1], a[mf][2], a[mf][3],
                      aS + offA + mf * 16 * BK * 4);
            uint32_t b[4][2];
            uint32_t offB = rowB * (BK * 4) + ((((ks << 1) + halfB) ^ (rowB & 7)) << 4);
#pragma unroll
            for (int bf = 0; bf < 2; bf++)
                LDSM4(b[2*bf][0], b[2*bf][1], b[2*bf+1][0], b[2*bf+1][1],
                      bS + offB + bf * 16 * BK * 4);
#pragma unroll
            for (int mf = 0; mf < 4; mf++)
#pragma unroll
                for (int nf = 0; nf < 4; nf++)
                    mma_tf32(acc[mf][nf], a[mf], b[nf]);
        }
    }

    const int rbase = m0 + wm + (lane >> 2);
    const int cbase = wn + (lane & 3) * 2;

    if (MODE == 1) {
#pragma unroll
        for (int mf = 0; mf < 4; mf++)
#pragma unroll
            for (int nf = 0; nf < 4; nf++) {
                int r = rbase + mf * 16;
                int e = n0 + cbase + nf * 8;
                *reinterpret_cast<float2*>(&Cout[(size_t)r * N + e]) =
                    make_float2(acc[mf][nf][0], acc[mf][nf][1]);
                *reinterpret_cast<float2*>(&Cout[(size_t)(r + 8) * N + e]) =
                    make_float2(acc[mf][nf][2], acc[mf][nf][3]);
            }
    } else {
        float* dst; int stride; int coloff;
        if (n0 + BN <= DIN)            { dst = g_z;     stride = DIN;   coloff = n0; }
        else if (n0 + BN <= DIN+CONVD) { dst = g_xbc;   stride = CONVD; coloff = n0 - DIN; }
        else                           { dst = g_dtraw; stride = NH;    coloff = n0 - DIN - CONVD; }
#pragma unroll
        for (int mf = 0; mf < 4; mf++)
#pragma unroll
            for (int nf = 0; nf < 4; nf++) {
                int cc = cbase + nf * 8;
                if (stride == NH && cc >= NH) continue;
                int r = rbase + mf * 16;
                int e = coloff + cc;
                *reinterpret_cast<float2*>(&dst[(size_t)r * stride + e]) =
                    make_float2(acc[mf][nf][0], acc[mf][nf][1]);
                *reinterpret_cast<float2*>(&dst[(size_t)(r + 8) * stride + e]) =
                    make_float2(acc[mf][nf][2], acc[mf][nf][3]);
            }
    }
}

// ---------------- depthwise causal conv + silu (sliding window, 4 l/thread) -
__global__ __launch_bounds__(256)
void conv_kernel(const float* __restrict__ conv_w,
                 const float* __restrict__ conv_b) {
    long idx = (long)blockIdx.x * blockDim.x + threadIdx.x;
    if (idx >= (long)(BL/4) * CONVD) return;
    int c   = (int)(idx % CONVD);
    int blq = (int)(idx / CONVD);
    int lq  = blq % (SEQ/4);
    int b   = blq / (SEQ/4);
    int l0  = lq * 4;
    size_t rowbase = ((size_t)b * SEQ + l0) * CONVD + c;

    float w0 = conv_w[c*4+0], w1 = conv_w[c*4+1],
          w2 = conv_w[c*4+2], w3 = conv_w[c*4+3];
    float xm3 = 0.f, xm2 = 0.f, xm1 = 0.f;
    if (l0 > 0) {
        xm3 = g_xbc[rowbase - 3*(size_t)CONVD];
        xm2 = g_xbc[rowbase - 2*(size_t)CONVD];
        xm1 = g_xbc[rowbase - 1*(size_t)CONVD];
    }
    float x0 = g_xbc[rowbase];
    float x1 = g_xbc[rowbase + 1*(size_t)CONVD];
    float x2 = g_xbc[rowbase + 2*(size_t)CONVD];
    float x3 = g_xbc[rowbase + 3*(size_t)CONVD];
    float bias = conv_b[c];

    float a0 = bias + xm3*w0 + xm2*w1 + xm1*w2 + x0*w3;
    float a1 = bias + xm2*w0 + xm1*w1 + x0 *w2 + x1*w3;
    float a2 = bias + xm1*w0 + x0 *w1 + x1 *w2 + x2*w3;
    float a3 = bias + x0 *w0 + x1 *w1 + x2 *w2 + x3*w3;
    float v0 = silu_fast(a0);
    float v1 = silu_fast(a1);
    float v2 = silu_fast(a2);
    float v3 = silu_fast(a3);

    int bl = b * SEQ + l0;
    if (c < DIN) {
        g_x[(size_t)bl * DIN + c]         = v0;
        g_x[(size_t)(bl+1) * DIN + c]     = v1;
        g_x[(size_t)(bl+2) * DIN + c]     = v2;
        g_x[(size_t)(bl+3) * DIN + c]     = v3;
    } else if (c < DIN + DS) {
        int cc = c - DIN;
        g_Bc[(size_t)bl * DS + cc]        = v0;
        g_Bc[(size_t)(bl+1) * DS + cc]    = v1;
        g_Bc[(size_t)(bl+2) * DS + cc]    = v2;
        g_Bc[(size_t)(bl+3) * DS + cc]    = v3;
    } else {
        int cc = c - DIN - DS;
        g_Cc[(size_t)bl * DS + cc]        = v0;
        g_Cc[(size_t)(bl+1) * DS + cc]    = v1;
        g_Cc[(size_t)(bl+2) * DS + cc]    = v2;
        g_Cc[(size_t)(bl+3) * DS + cc]    = v3;
    }
}

// ---------------- softplus(dt) + per-chunk cumsum of dA ---------------------
__global__ __launch_bounds__(256)
void dtscan_kernel(const float* __restrict__ dt_bias,
                   const float* __restrict__ A_log) {
    int blk = blockIdx.x;
    int h  = blk % NH;
    int bc = blk / NH;
    int c  = bc % NC;
    int b  = bc / NC;
    int s  = threadIdx.x;
    int bl = b * SEQ + c * CHK + s;

    float xv = g_dtraw[bl * NH + h] + dt_bias[h];
    float dt = fmaxf(xv, 0.f) + log1pf(expf(-fabsf(xv)));
    g_dt[bl * NH + h] = dt;
    float A  = -expf(A_log[h]);
    float dA = dt * A;

    __shared__ float sc[CHK];
    sc[s] = dA;
    __syncthreads();
    for (int off = 1; off < CHK; off <<= 1) {
        float v = (s >= off) ? sc[s - off] : 0.f;
        __syncthreads();
        sc[s] += v;
        __syncthreads();
    }
    float cum = sc[s];
    g_ecum[blk * CHK + s] = expf(cum);
    g_r[blk * CHK + s]    = expf(dA);
    if (s == CHK - 1) g_cdecay[blk] = expf(cum);
}

// ---------------- GT[b,c,z,s] = dot(C[s], B[z]) -----------------------------
__global__ __launch_bounds__(256)
void gmat_kernel() {
    int bid = blockIdx.x;
    int bc  = bid >> 8;
    int t   = bid & 255;
    int z0  = (t >> 4) * 16;
    int s0  = (t & 15) * 16;
    int b = bc / NC, c = bc % NC;
    int blb = b * SEQ + c * CHK;
    __shared__ float Bsm[16][65];
    __shared__ float Csm[16][65];
    int tid = threadIdx.x;
#pragma unroll
    for (int t4 = 0; t4 < 4; t4++) {
        int i = tid + t4 * 256;
        int row = i >> 6, n = i & 63;
        Bsm[row][n] = g_Bc[(size_t)(blb + z0 + row) * DS + n];
        Csm[row][n] = g_Cc[(size_t)(blb + s0 + row) * DS + n];
    }
    __syncthreads();
    int zl = tid >> 4, sl = tid & 15;
    float acc = 0.f;
#pragma unroll
    for (int n = 0; n < 64; n++) acc += Csm[sl][n] * Bsm[zl][n];
    g_GT[((size_t)bc * CHK + (z0 + zl)) * CHK + (s0 + sl)] = acc;
}

// ---------------- per-chunk states[p,n] -------------------------------------
__global__ __launch_bounds__(256)
void states_kernel() {
    int blk = blockIdx.x;
    int h  = blk % NH;
    int bc = blk / NH;
    int c  = bc % NC;
    int b  = bc / NC;
    int blb = b * SEQ + c * CHK;
    int tid = threadIdx.x;

    __shared__ float coef[CHK];
    __shared__ float xs[16][128];
    __shared__ float Bsm2[16][64];

    {
        int s = tid;
        coef[s] = (s < CHK - 1) ? g_r[blk * CHK + s + 1] : 1.f;
        __syncthreads();
        for (int off = 1; off < CHK; off <<= 1) {
            float v = (s + off < CHK) ? coef[s + off] : 1.f;
            __syncthreads();
            coef[s] *= v;
            __syncthreads();
        }
        coef[s] *= g_dt[(blb + s) * NH + h];
        __syncthreads();
    }

    int n  = tid & 63;
    int pg = tid >> 6;
    float acc[32];
#pragma unroll
    for (int j = 0; j < 32; j++) acc[j] = 0.f;

    for (int s0 = 0; s0 < CHK; s0 += 16) {
#pragma unroll
        for (int t8 = 0; t8 < 8; t8++) {
            int i = tid + t8 * 256;
            int ss = i >> 7, p = i & 127;
            xs[ss][p] = g_x[(size_t)(blb + s0 + ss) * DIN + h * DH + p];
        }
#pragma unroll
        for (int t4 = 0; t4 < 4; t4++) {
            int i = tid + t4 * 256;
            int ss = i >> 6, nn = i & 63;
            Bsm2[ss][nn] = g_Bc[(size_t)(blb + s0 + ss) * DS + nn];
        }
        __syncthreads();
#pragma unroll
        for (int ss = 0; ss < 16; ss++) {
            float w = Bsm2[ss][n] * coef[s0 + ss];
            const float4* xv = reinterpret_cast<const float4*>(&xs[ss][pg * 32]);
#pragma unroll
            for (int j4 = 0; j4 < 8; j4++) {
                float4 v = xv[j4];
                acc[j4 * 4 + 0] += w * v.x;
                acc[j4 * 4 + 1] += w * v.y;
                acc[j4 * 4 + 2] += w * v.z;
                acc[j4 * 4 + 3] += w * v.w;
            }
        }
        __syncthreads();
    }
    size_t base = (size_t)blk * DH * DS;
#pragma unroll
    for (int j = 0; j < 32; j++)
        g_states[base + (size_t)(pg * 32 + j) * DS + n] = acc[j];
}

// ---------------- sequential scan over chunks -------------------------------
__global__ __launch_bounds__(256)
void chunkscan_kernel() {
    int bid = blockIdx.x;
    int h = bid % NH, b = bid / NH;
    int tid = threadIdx.x;
    float carry[32];
#pragma unroll
    for (int j = 0; j < 32; j++) carry[j] = 0.f;
    for (int c = 0; c < NC; c++) {
        int blk = (b * NC + c) * NH + h;
        size_t base = (size_t)blk * DH * DS;
        float cd = g_cdecay[blk];
#pragma unroll
        for (int j = 0; j < 32; j++) {
            size_t e = base + (size_t)j * 256 + tid;
            g_prev[e] = carry[j];
            carry[j] = carry[j] * cd + g_states[e];
        }
    }
}

// ---------------- Y = Y_diag + Y_off + x*D ----------------------------------
__global__ __launch_bounds__(256)
void y_kernel(const float* __restrict__ Din) {
    int blk = blockIdx.x;
    int pt  = blockIdx.y;
    int h  = blk % NH;
    int bc = blk / NH;
    int c  = bc % NC;
    int b  = bc / NC;
    int blb = b * SEQ + c * CHK;
    int p0 = pt * 32;
    int s  = threadIdx.x;

    __shared__ float rs[CHK];
    __shared__ float prevT[DS][33];
    __shared__ float xdts[64][32];

    rs[s] = g_r[blk * CHK + s];
    size_t pbase = (size_t)blk * DH * DS;
#pragma unroll
    for (int t8 = 0; t8 < 8; t8++) {
        int i = s + t8 * 256;
        int p = i >> 6, n = i & 63;
        prevT[n][p] = g_prev[pbase + (size_t)(p0 + p) * DS + n];
    }
    __syncthreads();

    float acc[32];
    float Dh = Din[h];
    {
        const float4* xv = reinterpret_cast<const float4*>(
            &g_x[(size_t)(blb + s) * DIN + h * DH + p0]);
#pragma unroll
        for (int j4 = 0; j4 < 8; j4++) {
            float4 v = xv[j4];
            acc[4 * j4 + 0] = Dh * v.x;
            acc[4 * j4 + 1] = Dh * v.y;
            acc[4 * j4 + 2] = Dh * v.z;
            acc[4 * j4 + 3] = Dh * v.w;
        }
    }
    {
        float es = g_ecum[blk * CHK + s];
        const float* Crow = &g_Cc[(size_t)(blb + s) * DS];
#pragma unroll
        for (int n = 0; n < 64; n++) {
            float cn = es * __ldg(&Crow[n]);
#pragma unroll
            for (int j = 0; j < 32; j++) acc[j] += cn * prevT[n][j];
        }
    }
    float w = 0.f;
    for (int zt = 3; zt >= 0; zt--) {
        int z0 = zt * 64;
        bool needed = (s >= z0) && ((s < z0 + 64) || (w > 0.f));
        if (__syncthreads_count(needed) == 0) continue;
#pragma unroll
        for (int t8 = 0; t8 < 8; t8++) {
            int i = s + t8 * 256;
            int zz = i >> 5, p = i & 31;
            int z = z0 + zz;
            xdts[zz][p] = g_x[(size_t)(blb + z) * DIN + h * DH + p0 + p]
                        * g_dt[(blb + z) * NH + h];
        }
        __syncthreads();
        if (z0 <= s) {
            for (int zz = 63; zz >= 0; zz--) {
                int z = z0 + zz;
                if (z > s) continue;
                if (z < s && w == 0.f) break;
                float gt = __ldg(&g_GT[((size_t)bc * CHK + z) * CHK + s]);
                if (z == s) w = 1.f;
                if (w > 0.f) {
                    float g = gt * w;
                    const float4* xv = reinterpret_cast<const float4*>(&xdts[zz][0]);
#pragma unroll
                    for (int j4 = 0; j4 < 8; j4++) {
                        float4 v = xv[j4];
                        acc[4 * j4 + 0] += g * v.x;
                        acc[4 * j4 + 1] += g * v.y;
                        acc[4 * j4 + 2] += g * v.z;
                        acc[4 * j4 + 3] += g * v.w;
                    }
                }
                w *= rs[z];
            }
        }
        __syncthreads();
    }
    float4* yo = reinterpret_cast<float4*>(
        &g_y[(size_t)(blb + s) * DIN + h * DH + p0]);
#pragma unroll
    for (int j4 = 0; j4 < 8; j4++)
        yo[j4] = make_float4(acc[4 * j4 + 0], acc[4 * j4 + 1],
                             acc[4 * j4 + 2], acc[4 * j4 + 3]);
}

// ---------------- gating + RMSNorm (output tf32-rounded for GEMM2) ----------
__global__ __launch_bounds__(256)
void norm_kernel(const float* __restrict__ norm_w) {
    int row = blockIdx.x;
    int tid = threadIdx.x;
    size_t base = (size_t)row * DIN;
    float vals[16];
    float ssum = 0.f;
#pragma unroll
    for (int j = 0; j < 16; j++) {
        int e = j * 256 + tid;
        float y = g_y[base + e];
        float z = g_z[base + e];
        float yg = y * silu_fast(z);
        vals[j] = yg;
        ssum += yg * yg;
    }
    __shared__ float red[8];
#pragma unroll
    for (int off = 16; off > 0; off >>= 1)
        ssum += __shfl_down_sync(0xffffffffu, ssum, off);
    if ((tid & 31) == 0) red[tid >> 5] = ssum;
    __syncthreads();
    if (tid == 0) {
        float t = 0.f;
#pragma unroll
        for (int i = 0; i < 8; i++) t += red[i];
        red[0] = t;
    }
    __syncthreads();
    float scale = rsqrtf(red[0] * (1.0f / DIN) + 1e-5f);
#pragma unroll
    for (int j = 0; j < 16; j++) {
        int e = j * 256 + tid;
        g_y[base + e] = rna_tf32(vals[j] * scale * norm_w[e]);
    }
}

// ---------------- launch ----------------------------------------------------
extern "C" void kernel_launch(void* const* d_in, const int* in_sizes, int n_in,
                              void* d_out, int out_size) {
    (void)in_sizes; (void)n_in; (void)out_size;
    const float* u       = (const float*)d_in[0];
    const float* W_in    = (const float*)d_in[1];
    const float* conv_w  = (const float*)d_in[2];
    const float* conv_b  = (const float*)d_in[3];
    const float* dt_bias = (const float*)d_in[4];
    const float* A_log   = (const float*)d_in[5];
    const float* Dp      = (const float*)d_in[6];
    const float* norm_w  = (const float*)d_in[7];
    const float* W_out   = (const float*)d_in[8];
    float* out = (float*)d_out;

    void *uP, *WinP, *WoutP, *yP;
    cudaGetSymbolAddress(&uP, g_u);
    cudaGetSymbolAddress(&WinP, g_Win);
    cudaGetSymbolAddress(&WoutP, g_Wout);
    cudaGetSymbolAddress(&yP, g_y);

    cudaFuncSetAttribute(gemm_mma<0>, cudaFuncAttributeMaxDynamicSharedMemorySize,
                         GSMEM_BYTES);
    cudaFuncSetAttribute(gemm_mma<1>, cudaFuncAttributeMaxDynamicSharedMemorySize,
                         GSMEM_BYTES);

    // merged tf32 rna prep for u / W_in / W_out
    int n4all = N4_U + N4_WIN + N4_WOUT;
    prep_round_all<<<(n4all + 255) / 256, 256>>>(u, W_in, W_out);

    // in-projection: [BL, DPROJ] = u @ W_in^T
    dim3 g1((DPROJ + BN - 1) / BN, BL / BM);     // 66 x 64
    gemm_mma<0><<<g1, 256, GSMEM_BYTES>>>((const float*)uP, (const float*)WinP,
                                          nullptr, DPROJ, DM);

    long total = (long)(BL/4) * CONVD;
    conv_kernel<<<(unsigned)((total + 255) / 256), 256>>>(conv_w, conv_b);

    dtscan_kernel<<<BATCH * NC * NH, 256>>>(dt_bias, A_log);
    gmat_kernel<<<BATCH * NC * 256, 256>>>();
    states_kernel<<<BATCH * NC * NH, 256>>>();
    chunkscan_kernel<<<BATCH * NH, 256>>>();

    dim3 gy(BATCH * NC * NH, 4);
    y_kernel<<<gy, 256>>>(Dp);

    norm_kernel<<<BL, 256>>>(norm_w);

    // out-projection: [BL, DM] = yn @ W_out^T
    dim3 g2(DM / BN, BL / BM);                   // 16 x 64
    gemm_mma<1><<<g2, 256, GSMEM_BYTES>>>((const float*)yP, (const float*)WoutP,
                                          out, DM, DIN);
}

// round 16
// speedup vs baseline: 1.6821x; 1.6821x over previous
#include <cuda_runtime.h>
#include <math.h>
#include <stdint.h>

#define DM     2048
#define DIN    4096
#define NH     32
#define DH     128
#define DS     64
#define NC     16
#define CHK    256
#define CONVD  4224
#define DPROJ  8352
#define BATCH  2
#define SEQ    4096
#define BL     (BATCH*SEQ)

// ---------------- scratch (device globals; no allocations allowed) ----------
__device__ __align__(1024) float g_z[BL*DIN];
__device__ __align__(1024) float g_xbc[BL*CONVD];
__device__ __align__(1024) float g_dtraw[BL*NH];
__device__ __align__(1024) float g_x[BL*DIN];
__device__ __align__(1024) float g_Bc[BL*DS];
__device__ __align__(1024) float g_Cc[BL*DS];
__device__ float g_dt[BL*NH];
__device__ float g_r[BATCH*NC*NH*CHK];
__device__ float g_ecum[BATCH*NC*NH*CHK];
__device__ float g_cdecay[BATCH*NC*NH];
__device__ float g_GT[BATCH*NC*CHK*CHK];
__device__ float g_states[BATCH*NC*NH*DH*DS];
__device__ float g_prev[BATCH*NC*NH*DH*DS];
__device__ __align__(1024) float g_y[BL*DIN];
// tf32-rounded GEMM inputs
__device__ __align__(1024) float g_u[BL*DM];
__device__ __align__(1024) float g_Win[DPROJ*DM];
__device__ __align__(1024) float g_Wout[DM*DIN];

__device__ __forceinline__ float rna_tf32(float x) {
    float y;
    asm("cvt.rna.tf32.f32 %0, %1;" : "=f"(y) : "f"(x));
    return y;
}

// silu with 1 MUFU (EX2) + FMA-pipe reciprocal (bit trick + 3 Newton, ~1e-7)
__device__ __forceinline__ float silu_fast(float x) {
    float e = __expf(-x);
    e = fminf(e, 1e30f);                 // keep d finite for the bit trick
    float d = 1.f + e;
    float r = __uint_as_float(0x7EF311C3u - __float_as_uint(d));
    r = r * (2.f - d * r);
    r = r * (2.f - d * r);
    r = r * (2.f - d * r);
    return x * r;
}

// ---------------- merged prep: round u / W_in / W_out to tf32 (rna) ---------
#define N4_U    (BL*DM/4)
#define N4_WIN  (DPROJ*DM/4)
#define N4_WOUT (DM*DIN/4)
__global__ __launch_bounds__(256)
void prep_round_all(const float* __restrict__ u,
                    const float* __restrict__ W_in,
                    const float* __restrict__ W_out) {
    int i = blockIdx.x * 256 + threadIdx.x;
    const float* src; float* dst; int off;
    if (i < N4_U)                     { src = u;     dst = g_u;    off = i; }
    else if (i < N4_U + N4_WIN)       { src = W_in;  dst = g_Win;  off = i - N4_U; }
    else if (i < N4_U + N4_WIN + N4_WOUT) { src = W_out; dst = g_Wout; off = i - N4_U - N4_WIN; }
    else return;
    float4 v = reinterpret_cast<const float4*>(src)[off];
    v.x = rna_tf32(v.x); v.y = rna_tf32(v.y);
    v.z = rna_tf32(v.z); v.w = rna_tf32(v.w);
    reinterpret_cast<float4*>(dst)[off] = v;
}

// ======================= mma.sync tf32 GEMM (R11 flat loop, untouched) ======
#define BM 128
#define BN 128
#define BK 32
#define GSTG 3
#define A_STG_F (BM*BK)
#define B_STG_F (BN*BK)
#define GSMEM_BYTES (GSTG*(A_STG_F+B_STG_F)*4)   // 98304

__device__ __forceinline__ uint32_t smem_u32(const void* p) {
    uint32_t a;
    asm("{ .reg .u64 t; cvta.to.shared.u64 t, %1; cvt.u32.u64 %0, t; }"
        : "=r"(a) : "l"(p));
    return a;
}
__device__ __forceinline__ void cp_async16(uint32_t dst, const void* src, int srcsize) {
    asm volatile("cp.async.cg.shared.global [%0], [%1], 16, %2;"
                 :: "r"(dst), "l"(src), "r"(srcsize) : "memory");
}
#define CP_COMMIT() asm volatile("cp.async.commit_group;" ::: "memory")
#define CP_WAIT1()  asm volatile("cp.async.wait_group 1;" ::: "memory")

#define LDSM4(r0, r1, r2, r3, addr) \
    asm volatile("ldmatrix.sync.aligned.m8n8.x4.shared.b16 {%0,%1,%2,%3}, [%4];" \
        : "=r"(r0), "=r"(r1), "=r"(r2), "=r"(r3) : "r"(addr))

__device__ __forceinline__ void mma_tf32(float* c, const uint32_t* a, const uint32_t* b) {
    asm volatile(
        "mma.sync.aligned.m16n8k8.row.col.f32.tf32.tf32.f32 "
        "{%0,%1,%2,%3}, {%4,%5,%6,%7}, {%8,%9}, {%0,%1,%2,%3};"
        : "+f"(c[0]), "+f"(c[1]), "+f"(c[2]), "+f"(c[3])
        : "r"(a[0]), "r"(a[1]), "r"(a[2]), "r"(a[3]), "r"(b[0]), "r"(b[1]));
}

// MODE 0: in-proj -> scatter into g_z / g_xbc / g_dtraw
// MODE 1: plain store to Cout with row stride N
template<int MODE>
__global__ __launch_bounds__(256, 2)
void gemm_mma(const float* __restrict__ A, const float* __restrict__ Bw,
              float* __restrict__ Cout, int N, int K) {
    extern __shared__ __align__(128) float smem[];
    const uint32_t aAddr0 = smem_u32(smem);
    const uint32_t bAddr0 = aAddr0 + GSTG * A_STG_F * 4;

    const int tid  = threadIdx.x;
    const int wid  = tid >> 5;
    const int lane = tid & 31;
    const int m0 = blockIdx.y * BM;
    const int n0 = blockIdx.x * BN;
    const int wm = (wid >> 2) * 64;
    const int wn = (wid & 3) * 32;
    const int nk = K / BK;

    float acc[4][4][4];
#pragma unroll
    for (int i = 0; i < 4; i++)
#pragma unroll
        for (int j = 0; j < 4; j++)
#pragma unroll
            for (int q = 0; q < 4; q++) acc[i][j][q] = 0.f;

    const int t4 = lane >> 3;
    const int rowA = wm + ((t4 & 1) << 3) + (lane & 7);
    const int halfA = t4 >> 1;
    const int rowB = wn + ((t4 >> 1) << 3) + (lane & 7);
    const int halfB = t4 & 1;

    auto issue_loads = [&](int stage, int kiter) {
        const float* Ag = A + (size_t)m0 * K + kiter * BK;
        uint32_t aS = aAddr0 + stage * A_STG_F * 4;
#pragma unroll
        for (int i = 0; i < 4; i++) {
            int lin = i * 256 + tid;
            int row = lin >> 3, c = lin & 7;
            uint32_t dst = aS + (row * BK + ((c ^ (row & 7)) << 2)) * 4;
            cp_async16(dst, Ag + (size_t)row * K + c * 4, 16);
        }
        const float* Bg = Bw + (size_t)kiter * BK;
        uint32_t bS = bAddr0 + stage * B_STG_F * 4;
#pragma unroll
        for (int i = 0; i < 4; i++) {
            int lin = i * 256 + tid;
            int row = lin >> 3, c = lin & 7;
            int gr = n0 + row;
            int ok = (gr < N) ? 16 : 0;
            uint32_t dst = bS + (row * BK + ((c ^ (row & 7)) << 2)) * 4;
            cp_async16(dst, Bg + (size_t)(ok ? gr : 0) * K + c * 4, ok);
        }
    };

    issue_loads(0, 0); CP_COMMIT();
    issue_loads(1, 1); CP_COMMIT();

    for (int i = 0; i < nk; i++) {
        CP_WAIT1();
        __syncthreads();
        int nxt = i + 2;
        if (nxt < nk) issue_loads(nxt % GSTG, nxt);
        CP_COMMIT();

        int st = i % GSTG;
        uint32_t aS = aAddr0 + st * A_STG_F * 4;
        uint32_t bS = bAddr0 + st * B_STG_F * 4;
#pragma unroll
        for (int ks = 0; ks < 4; ks++) {
            uint32_t a[4][4];
            uint32_t offA = rowA * (BK * 4) + ((((ks << 1) + halfA) ^ (rowA & 7)) << 4);
#pragma unroll
            for (int mf = 0; mf < 4; mf++)
                LDSM4(a[mf][0], a[mf][1], a[mf][2], a[mf][3],
                      aS + offA + mf * 16 * BK * 4);
            uint32_t b[4][2];
            uint32_t offB = rowB * (BK * 4) + ((((ks << 1) + halfB) ^ (rowB & 7)) << 4);
#pragma unroll
            for (int bf = 0; bf < 2; bf++)
                LDSM4(b[2*bf][0], b[2*bf][1], b[2*bf+1][0], b[2*bf+1][1],
                      bS + offB + bf * 16 * BK * 4);
#pragma unroll
            for (int mf = 0; mf < 4; mf++)
#pragma unroll
                for (int nf = 0; nf < 4; nf++)
                    mma_tf32(acc[mf][nf], a[mf], b[nf]);
        }
    }

    const int rbase = m0 + wm + (lane >> 2);
    const int cbase = wn + (lane & 3) * 2;

    if (MODE == 1) {
#pragma unroll
        for (int mf = 0; mf < 4; mf++)
#pragma unroll
            for (int nf = 0; nf < 4; nf++) {
                int r = rbase + mf * 16;
                int e = n0 + cbase + nf * 8;
                *reinterpret_cast<float2*>(&Cout[(size_t)r * N + e]) =
                    make_float2(acc[mf][nf][0], acc[mf][nf][1]);
                *reinterpret_cast<float2*>(&Cout[(size_t)(r + 8) * N + e]) =
                    make_float2(acc[mf][nf][2], acc[mf][nf][3]);
            }
    } else {
        float* dst; int stride; int coloff;
        if (n0 + BN <= DIN)            { dst = g_z;     stride = DIN;   coloff = n0; }
        else if (n0 + BN <= DIN+CONVD) { dst = g_xbc;   stride = CONVD; coloff = n0 - DIN; }
        else                           { dst = g_dtraw; stride = NH;    coloff = n0 - DIN - CONVD; }
#pragma unroll
        for (int mf = 0; mf < 4; mf++)
#pragma unroll
            for (int nf = 0; nf < 4; nf++) {
                int cc = cbase + nf * 8;
                if (stride == NH && cc >= NH) continue;
                int r = rbase + mf * 16;
                int e = coloff + cc;
                *reinterpret_cast<float2*>(&dst[(size_t)r * stride + e]) =
                    make_float2(acc[mf][nf][0], acc[mf][nf][1]);
                *reinterpret_cast<float2*>(&dst[(size_t)(r + 8) * stride + e]) =
                    make_float2(acc[mf][nf][2], acc[mf][nf][3]);
            }
    }
}

// ---------------- depthwise causal conv + silu (sliding window, 4 l/thread) -
__global__ __launch_bounds__(256)
void conv_kernel(const float* __restrict__ conv_w,
                 const float* __restrict__ conv_b) {
    long idx = (long)blockIdx.x * blockDim.x + threadIdx.x;
    if (idx >= (long)(BL/4) * CONVD) return;
    int c   = (int)(idx % CONVD);
    int blq = (int)(idx / CONVD);
    int lq  = blq % (SEQ/4);
    int b   = blq / (SEQ/4);
    int l0  = lq * 4;
    size_t rowbase = ((size_t)b * SEQ + l0) * CONVD + c;

    float w0 = conv_w[c*4+0], w1 = conv_w[c*4+1],
          w2 = conv_w[c*4+2], w3 = conv_w[c*4+3];
    float xm3 = 0.f, xm2 = 0.f, xm1 = 0.f;
    if (l0 > 0) {
        xm3 = g_xbc[rowbase - 3*(size_t)CONVD];
        xm2 = g_xbc[rowbase - 2*(size_t)CONVD];
        xm1 = g_xbc[rowbase - 1*(size_t)CONVD];
    }
    float x0 = g_xbc[rowbase];
    float x1 = g_xbc[rowbase + 1*(size_t)CONVD];
    float x2 = g_xbc[rowbase + 2*(size_t)CONVD];
    float x3 = g_xbc[rowbase + 3*(size_t)CONVD];
    float bias = conv_b[c];

    float a0 = bias + xm3*w0 + xm2*w1 + xm1*w2 + x0*w3;
    float a1 = bias + xm2*w0 + xm1*w1 + x0 *w2 + x1*w3;
    float a2 = bias + xm1*w0 + x0 *w1 + x1 *w2 + x2*w3;
    float a3 = bias + x0 *w0 + x1 *w1 + x2 *w2 + x3*w3;
    float v0 = silu_fast(a0);
    float v1 = silu_fast(a1);
    float v2 = silu_fast(a2);
    float v3 = silu_fast(a3);

    int bl = b * SEQ + l0;
    if (c < DIN) {
        g_x[(size_t)bl * DIN + c]         = v0;
        g_x[(size_t)(bl+1) * DIN + c]     = v1;
        g_x[(size_t)(bl+2) * DIN + c]     = v2;
        g_x[(size_t)(bl+3) * DIN + c]     = v3;
    } else if (c < DIN + DS) {
        int cc = c - DIN;
        g_Bc[(size_t)bl * DS + cc]        = v0;
        g_Bc[(size_t)(bl+1) * DS + cc]    = v1;
        g_Bc[(size_t)(bl+2) * DS + cc]    = v2;
        g_Bc[(size_t)(bl+3) * DS + cc]    = v3;
    } else {
        int cc = c - DIN - DS;
        g_Cc[(size_t)bl * DS + cc]        = v0;
        g_Cc[(size_t)(bl+1) * DS + cc]    = v1;
        g_Cc[(size_t)(bl+2) * DS + cc]    = v2;
        g_Cc[(size_t)(bl+3) * DS + cc]    = v3;
    }
}

// ---------------- softplus(dt) + per-chunk cumsum of dA ---------------------
__global__ __launch_bounds__(256)
void dtscan_kernel(const float* __restrict__ dt_bias,
                   const float* __restrict__ A_log) {
    int blk = blockIdx.x;
    int h  = blk % NH;
    int bc = blk / NH;
    int c  = bc % NC;
    int b  = bc / NC;
    int s  = threadIdx.x;
    int bl = b * SEQ + c * CHK + s;

    float xv = g_dtraw[bl * NH + h] + dt_bias[h];
    float dt = fmaxf(xv, 0.f) + log1pf(expf(-fabsf(xv)));
    g_dt[bl * NH + h] = dt;
    float A  = -expf(A_log[h]);
    float dA = dt * A;

    __shared__ float sc[CHK];
    sc[s] = dA;
    __syncthreads();
    for (int off = 1; off < CHK; off <<= 1) {
        float v = (s >= off) ? sc[s - off] : 0.f;
        __syncthreads();
        sc[s] += v;
        __syncthreads();
    }
    float cum = sc[s];
    g_ecum[blk * CHK + s] = expf(cum);
    g_r[blk * CHK + s]    = expf(dA);
    if (s == CHK - 1) g_cdecay[blk] = expf(cum);
}

// ---------------- GT[b,c,z,s] = dot(C[s], B[z]) -----------------------------
__global__ __launch_bounds__(256)
void gmat_kernel() {
    int bid = blockIdx.x;
    int bc  = bid >> 8;
    int t   = bid & 255;
    int z0  = (t >> 4) * 16;
    int s0  = (t & 15) * 16;
    int b = bc / NC, c = bc % NC;
    int blb = b * SEQ + c * CHK;
    __shared__ float Bsm[16][65];
    __shared__ float Csm[16][65];
    int tid = threadIdx.x;
#pragma unroll
    for (int t4 = 0; t4 < 4; t4++) {
        int i = tid + t4 * 256;
        int row = i >> 6, n = i & 63;
        Bsm[row][n] = g_Bc[(size_t)(blb + z0 + row) * DS + n];
        Csm[row][n] = g_Cc[(size_t)(blb + s0 + row) * DS + n];
    }
    __syncthreads();
    int zl = tid >> 4, sl = tid & 15;
    float acc = 0.f;
#pragma unroll
    for (int n = 0; n < 64; n++) acc += Csm[sl][n] * Bsm[zl][n];
    g_GT[((size_t)bc * CHK + (z0 + zl)) * CHK + (s0 + sl)] = acc;
}

// ---------------- per-chunk states[p,n] -------------------------------------
__global__ __launch_bounds__(256)
void states_kernel() {
    int blk = blockIdx.x;
    int h  = blk % NH;
    int bc = blk / NH;
    int c  = bc % NC;
    int b  = bc / NC;
    int blb = b * SEQ + c * CHK;
    int tid = threadIdx.x;

    __shared__ float coef[CHK];
    __shared__ float xs[16][128];
    __shared__ float Bsm2[16][64];

    {
        int s = tid;
        coef[s] = (s < CHK - 1) ? g_r[blk * CHK + s + 1] : 1.f;
        __syncthreads();
        for (int off = 1; off < CHK; off <<= 1) {
            float v = (s + off < CHK) ? coef[s + off] : 1.f;
            __syncthreads();
            coef[s] *= v;
            __syncthreads();
        }
        coef[s] *= g_dt[(blb + s) * NH + h];
        __syncthreads();
    }

    int n  = tid & 63;
    int pg = tid >> 6;
    float acc[32];
#pragma unroll
    for (int j = 0; j < 32; j++) acc[j] = 0.f;

    for (int s0 = 0; s0 < CHK; s0 += 16) {
#pragma unroll
        for (int t8 = 0; t8 < 8; t8++) {
            int i = tid + t8 * 256;
            int ss = i >> 7, p = i & 127;
            xs[ss][p] = g_x[(size_t)(blb + s0 + ss) * DIN + h * DH + p];
        }
#pragma unroll
        for (int t4 = 0; t4 < 4; t4++) {
            int i = tid + t4 * 256;
            int ss = i >> 6, nn = i & 63;
            Bsm2[ss][nn] = g_Bc[(size_t)(blb + s0 + ss) * DS + nn];
        }
        __syncthreads();
#pragma unroll
        for (int ss = 0; ss < 16; ss++) {
            float w = Bsm2[ss][n] * coef[s0 + ss];
            const float4* xv = reinterpret_cast<const float4*>(&xs[ss][pg * 32]);
#pragma unroll
            for (int j4 = 0; j4 < 8; j4++) {
                float4 v = xv[j4];
                acc[j4 * 4 + 0] += w * v.x;
                acc[j4 * 4 + 1] += w * v.y;
                acc[j4 * 4 + 2] += w * v.z;
                acc[j4 * 4 + 3] += w * v.w;
            }
        }
        __syncthreads();
    }
    size_t base = (size_t)blk * DH * DS;
#pragma unroll
    for (int j = 0; j < 32; j++)
        g_states[base + (size_t)(pg * 32 + j) * DS + n] = acc[j];
}

// ---------------- sequential scan over chunks -------------------------------
__global__ __launch_bounds__(256)
void chunkscan_kernel() {
    int bid = blockIdx.x;
    int h = bid % NH, b = bid / NH;
    int tid = threadIdx.x;
    float carry[32];
#pragma unroll
    for (int j = 0; j < 32; j++) carry[j] = 0.f;
    for (int c = 0; c < NC; c++) {
        int blk = (b * NC + c) * NH + h;
        size_t base = (size_t)blk * DH * DS;
        float cd = g_cdecay[blk];
#pragma unroll
        for (int j = 0; j < 32; j++) {
            size_t e = base + (size_t)j * 256 + tid;
            g_prev[e] = carry[j];
            carry[j] = carry[j] * cd + g_states[e];
        }
    }
}

// ---------------- Y = Y_diag + Y_off + x*D ----------------------------------
__global__ __launch_bounds__(256)
void y_kernel(const float* __restrict__ Din) {
    int blk = blockIdx.x;
    int pt  = blockIdx.y;
    int h  = blk % NH;
    int bc = blk / NH;
    int c  = bc % NC;
    int b  = bc / NC;
    int blb = b * SEQ + c * CHK;
    int p0 = pt * 32;
    int s  = threadIdx.x;

    __shared__ float rs[CHK];
    __shared__ float prevT[DS][33];
    __shared__ float xdts[64][32];

    rs[s] = g_r[blk * CHK + s];
    size_t pbase = (size_t)blk * DH * DS;
#pragma unroll
    for (int t8 = 0; t8 < 8; t8++) {
        int i = s + t8 * 256;
        int p = i >> 6, n = i & 63;
        prevT[n][p] = g_prev[pbase + (size_t)(p0 + p) * DS + n];
    }
    __syncthreads();

    float acc[32];
    float Dh = Din[h];
    {
        const float4* xv = reinterpret_cast<const float4*>(
            &g_x[(size_t)(blb + s) * DIN + h * DH + p0]);
#pragma unroll
        for (int j4 = 0; j4 < 8; j4++) {
            float4 v = xv[j4];
            acc[4 * j4 + 0] = Dh * v.x;
            acc[4 * j4 + 1] = Dh * v.y;
            acc[4 * j4 + 2] = Dh * v.z;
            acc[4 * j4 + 3] = Dh * v.w;
        }
    }
    {
        float es = g_ecum[blk * CHK + s];
        const float* Crow = &g_Cc[(size_t)(blb + s) * DS];
#pragma unroll
        for (int n = 0; n < 64; n++) {
            float cn = es * __ldg(&Crow[n]);
#pragma unroll
            for (int j = 0; j < 32; j++) acc[j] += cn * prevT[n][j];
        }
    }
    float w = 0.f;
    for (int zt = 3; zt >= 0; zt--) {
        int z0 = zt * 64;
        bool needed = (s >= z0) && ((s < z0 + 64) || (w > 0.f));
        if (__syncthreads_count(needed) == 0) continue;
#pragma unroll
        for (int t8 = 0; t8 < 8; t8++) {
            int i = s + t8 * 256;
            int zz = i >> 5, p = i & 31;
            int z = z0 + zz;
            xdts[zz][p] = g_x[(size_t)(blb + z) * DIN + h * DH + p0 + p]
                        * g_dt[(blb + z) * NH + h];
        }
        __syncthreads();
        if (z0 <= s) {
            for (int zz = 63; zz >= 0; zz--) {
                int z = z0 + zz;
                if (z > s) continue;
                if (z < s && w == 0.f) break;
                float gt = __ldg(&g_GT[((size_t)bc * CHK + z) * CHK + s]);
                if (z == s) w = 1.f;
                if (w > 0.f) {
                    float g = gt * w;
                    const float4* xv = reinterpret_cast<const float4*>(&xdts[zz][0]);
#pragma unroll
                    for (int j4 = 0; j4 < 8; j4++) {
                        float4 v = xv[j4];
                        acc[4 * j4 + 0] += g * v.x;
                        acc[4 * j4 + 1] += g * v.y;
                        acc[4 * j4 + 2] += g * v.z;
                        acc[4 * j4 + 3] += g * v.w;
                    }
                }
                w *= rs[z];
            }
        }
        __syncthreads();
    }
    float4* yo = reinterpret_cast<float4*>(
        &g_y[(size_t)(blb + s) * DIN + h * DH + p0]);
#pragma unroll
    for (int j4 = 0; j4 < 8; j4++)
        yo[j4] = make_float4(acc[4 * j4 + 0], acc[4 * j4 + 1],
                             acc[4 * j4 + 2], acc[4 * j4 + 3]);
}

// ---------------- gating + RMSNorm (output tf32-rounded for GEMM2) ----------
__global__ __launch_bounds__(256)
void norm_kernel(const float* __restrict__ norm_w) {
    int row = blockIdx.x;
    int tid = threadIdx.x;
    size_t base = (size_t)row * DIN;
    float vals[16];
    float ssum = 0.f;
#pragma unroll
    for (int j = 0; j < 16; j++) {
        int e = j * 256 + tid;
        float y = g_y[base + e];
        float z = g_z[base + e];
        float yg = y * silu_fast(z);
        vals[j] = yg;
        ssum += yg * yg;
    }
    __shared__ float red[8];
#pragma unroll
    for (int off = 16; off > 0; off >>= 1)
        ssum += __shfl_down_sync(0xffffffffu, ssum, off);
    if ((tid & 31) == 0) red[tid >> 5] = ssum;
    __syncthreads();
    if (tid == 0) {
        float t = 0.f;
#pragma unroll
        for (int i = 0; i < 8; i++) t += red[i];
        red[0] = t;
    }
    __syncthreads();
    float scale = rsqrtf(red[0] * (1.0f / DIN) + 1e-5f);
#pragma unroll
    for (int j = 0; j < 16; j++) {
        int e = j * 256 + tid;
        g_y[base + e] = rna_tf32(vals[j] * scale * norm_w[e]);
    }
}

// ---------------- launch ----------------------------------------------------
extern "C" void kernel_launch(void* const* d_in, const int* in_sizes, int n_in,
                              void* d_out, int out_size) {
    (void)in_sizes; (void)n_in; (void)out_size;
    const float* u       = (const float*)d_in[0];
    const float* W_in    = (const float*)d_in[1];
    const float* conv_w  = (const float*)d_in[2];
    const float* conv_b  = (const float*)d_in[3];
    const float* dt_bias = (const float*)d_in[4];
    const float* A_log   = (const float*)d_in[5];
    const float* Dp      = (const float*)d_in[6];
    const float* norm_w  = (const float*)d_in[7];
    const float* W_out   = (const float*)d_in[8];
    float* out = (float*)d_out;

    void *uP, *WinP, *WoutP, *yP;
    cudaGetSymbolAddress(&uP, g_u);
    cudaGetSymbolAddress(&WinP, g_Win);
    cudaGetSymbolAddress(&WoutP, g_Wout);
    cudaGetSymbolAddress(&yP, g_y);

    cudaFuncSetAttribute(gemm_mma<0>, cudaFuncAttributeMaxDynamicSharedMemorySize,
                         GSMEM_BYTES);
    cudaFuncSetAttribute(gemm_mma<1>, cudaFuncAttributeMaxDynamicSharedMemorySize,
                         GSMEM_BYTES);

    // merged tf32 rna prep for u / W_in / W_out
    int n4all = N4_U + N4_WIN + N4_WOUT;
    prep_round_all<<<(n4all + 255) / 256, 256>>>(u, W_in, W_out);

    // in-projection: [BL, DPROJ] = u @ W_in^T
    dim3 g1((DPROJ + BN - 1) / BN, BL / BM);     // 66 x 64
    gemm_mma<0><<<g1, 256, GSMEM_BYTES>>>((const float*)uP, (const float*)WinP,
                                          nullptr, DPROJ, DM);

    long total = (long)(BL/4) * CONVD;
    conv_kernel<<<(unsigned)((total + 255) / 256), 256>>>(conv_w, conv_b);

    dtscan_kernel<<<BATCH * NC * NH, 256>>>(dt_bias, A_log);
    gmat_kernel<<<BATCH * NC * 256, 256>>>();
    states_kernel<<<BATCH * NC * NH, 256>>>();
    chunkscan_kernel<<<BATCH * NH, 256>>>();

    dim3 gy(BATCH * NC * NH, 4);
    y_kernel<<<gy, 256>>>(Dp);

    norm_kernel<<<BL, 256>>>(norm_w);

    // out-projection: [BL, DM] = yn @ W_out^T
    dim3 g2(DM / BN, BL / BM);                   // 16 x 64
    gemm_mma<1><<<g2, 256, GSMEM_BYTES>>>((const float*)yP, (const float*)WoutP,
                                          out, DM, DIN);
}

// round 17
// speedup vs baseline: 1.7313x; 1.0293x over previous
#include <cuda_runtime.h>
#include <math.h>
#include <stdint.h>

#define DM     2048
#define DIN    4096
#define NH     32
#define DH     128
#define DS     64
#define NC     16
#define CHK    256
#define CONVD  4224
#define DPROJ  8352
#define BATCH  2
#define SEQ    4096
#define BL     (BATCH*SEQ)

// ---------------- scratch (device globals; no allocations allowed) ----------
__device__ __align__(1024) float g_z[BL*DIN];
__device__ __align__(1024) float g_xbc[BL*CONVD];
__device__ __align__(1024) float g_dtraw[BL*NH];
__device__ __align__(1024) float g_x[BL*DIN];
__device__ __align__(1024) float g_Bc[BL*DS];
__device__ __align__(1024) float g_Cc[BL*DS];
__device__ float g_dt[BL*NH];
__device__ float g_r[BATCH*NC*NH*CHK];
__device__ float g_ecum[BATCH*NC*NH*CHK];
__device__ float g_cdecay[BATCH*NC*NH];
__device__ float g_GT[BATCH*NC*CHK*CHK];
__device__ float g_states[BATCH*NC*NH*DH*DS];
__device__ float g_prev[BATCH*NC*NH*DH*DS];
__device__ __align__(1024) float g_y[BL*DIN];
// tf32-rounded GEMM inputs
__device__ __align__(1024) float g_u[BL*DM];
__device__ __align__(1024) float g_Win[DPROJ*DM];
__device__ __align__(1024) float g_Wout[DM*DIN];

__device__ __forceinline__ float rna_tf32(float x) {
    float y;
    asm("cvt.rna.tf32.f32 %0, %1;" : "=f"(y) : "f"(x));
    return y;
}

// silu with 1 MUFU (EX2) + FMA-pipe reciprocal (bit trick + 3 Newton, ~1e-7)
__device__ __forceinline__ float silu_fast(float x) {
    float e = __expf(-x);
    e = fminf(e, 1e30f);                 // keep d finite for the bit trick
    float d = 1.f + e;
    float r = __uint_as_float(0x7EF311C3u - __float_as_uint(d));
    r = r * (2.f - d * r);
    r = r * (2.f - d * r);
    r = r * (2.f - d * r);
    return x * r;
}

// ---------------- merged prep: round u / W_in / W_out to tf32 (rna) ---------
#define N4_U    (BL*DM/4)
#define N4_WIN  (DPROJ*DM/4)
#define N4_WOUT (DM*DIN/4)
__global__ __launch_bounds__(256)
void prep_round_all(const float* __restrict__ u,
                    const float* __restrict__ W_in,
                    const float* __restrict__ W_out) {
    int i = blockIdx.x * 256 + threadIdx.x;
    const float* src; float* dst; int off;
    if (i < N4_U)                     { src = u;     dst = g_u;    off = i; }
    else if (i < N4_U + N4_WIN)       { src = W_in;  dst = g_Win;  off = i - N4_U; }
    else if (i < N4_U + N4_WIN + N4_WOUT) { src = W_out; dst = g_Wout; off = i - N4_U - N4_WIN; }
    else return;
    float4 v = reinterpret_cast<const float4*>(src)[off];
    v.x = rna_tf32(v.x); v.y = rna_tf32(v.y);
    v.z = rna_tf32(v.z); v.w = rna_tf32(v.w);
    reinterpret_cast<float4*>(dst)[off] = v;
}

// ======================= mma.sync tf32 GEMM (R11 flat loop, untouched) ======
#define BM 128
#define BN 128
#define BK 32
#define GSTG 3
#define A_STG_F (BM*BK)
#define B_STG_F (BN*BK)
#define GSMEM_BYTES (GSTG*(A_STG_F+B_STG_F)*4)   // 98304

__device__ __forceinline__ uint32_t smem_u32(const void* p) {
    uint32_t a;
    asm("{ .reg .u64 t; cvta.to.shared.u64 t, %1; cvt.u32.u64 %0, t; }"
        : "=r"(a) : "l"(p));
    return a;
}
__device__ __forceinline__ void cp_async16(uint32_t dst, const void* src, int srcsize) {
    asm volatile("cp.async.cg.shared.global [%0], [%1], 16, %2;"
                 :: "r"(dst), "l"(src), "r"(srcsize) : "memory");
}
#define CP_COMMIT() asm volatile("cp.async.commit_group;" ::: "memory")
#define CP_WAIT1()  asm volatile("cp.async.wait_group 1;" ::: "memory")

#define LDSM4(r0, r1, r2, r3, addr) \
    asm volatile("ldmatrix.sync.aligned.m8n8.x4.shared.b16 {%0,%1,%2,%3}, [%4];" \
        : "=r"(r0), "=r"(r1), "=r"(r2), "=r"(r3) : "r"(addr))

__device__ __forceinline__ void mma_tf32(float* c, const uint32_t* a, const uint32_t* b) {
    asm volatile(
        "mma.sync.aligned.m16n8k8.row.col.f32.tf32.tf32.f32 "
        "{%0,%1,%2,%3}, {%4,%5,%6,%7}, {%8,%9}, {%0,%1,%2,%3};"
        : "+f"(c[0]), "+f"(c[1]), "+f"(c[2]), "+f"(c[3])
        : "r"(a[0]), "r"(a[1]), "r"(a[2]), "r"(a[3]), "r"(b[0]), "r"(b[1]));
}

// MODE 0: in-proj -> scatter into g_z / g_xbc / g_dtraw
// MODE 1: plain store to Cout with row stride N
template<int MODE>
__global__ __launch_bounds__(256, 2)
void gemm_mma(const float* __restrict__ A, const float* __restrict__ Bw,
              float* __restrict__ Cout, int N, int K) {
    extern __shared__ __align__(128) float smem[];
    const uint32_t aAddr0 = smem_u32(smem);
    const uint32_t bAddr0 = aAddr0 + GSTG * A_STG_F * 4;

    const int tid  = threadIdx.x;
    const int wid  = tid >> 5;
    const int lane = tid & 31;
    const int m0 = blockIdx.y * BM;
    const int n0 = blockIdx.x * BN;
    const int wm = (wid >> 2) * 64;
    const int wn = (wid & 3) * 32;
    const int nk = K / BK;

    float acc[4][4][4];
#pragma unroll
    for (int i = 0; i < 4; i++)
#pragma unroll
        for (int j = 0; j < 4; j++)
#pragma unroll
            for (int q = 0; q < 4; q++) acc[i][j][q] = 0.f;

    const int t4 = lane >> 3;
    const int rowA = wm + ((t4 & 1) << 3) + (lane & 7);
    const int halfA = t4 >> 1;
    const int rowB = wn + ((t4 >> 1) << 3) + (lane & 7);
    const int halfB = t4 & 1;

    auto issue_loads = [&](int stage, int kiter) {
        const float* Ag = A + (size_t)m0 * K + kiter * BK;
        uint32_t aS = aAddr0 + stage * A_STG_F * 4;
#pragma unroll
        for (int i = 0; i < 4; i++) {
            int lin = i * 256 + tid;
            int row = lin >> 3, c = lin & 7;
            uint32_t dst = aS + (row * BK + ((c ^ (row & 7)) << 2)) * 4;
            cp_async16(dst, Ag + (size_t)row * K + c * 4, 16);
        }
        const float* Bg = Bw + (size_t)kiter * BK;
        uint32_t bS = bAddr0 + stage * B_STG_F * 4;
#pragma unroll
        for (int i = 0; i < 4; i++) {
            int lin = i * 256 + tid;
            int row = lin >> 3, c = lin & 7;
            int gr = n0 + row;
            int ok = (gr < N) ? 16 : 0;
            uint32_t dst = bS + (row * BK + ((c ^ (row & 7)) << 2)) * 4;
            cp_async16(dst, Bg + (size_t)(ok ? gr : 0) * K + c * 4, ok);
        }
    };

    issue_loads(0, 0); CP_COMMIT();
    issue_loads(1, 1); CP_COMMIT();

    for (int i = 0; i < nk; i++) {
        CP_WAIT1();
        __syncthreads();
        int nxt = i + 2;
        if (nxt < nk) issue_loads(nxt % GSTG, nxt);
        CP_COMMIT();

        int st = i % GSTG;
        uint32_t aS = aAddr0 + st * A_STG_F * 4;
        uint32_t bS = bAddr0 + st * B_STG_F * 4;
#pragma unroll
        for (int ks = 0; ks < 4; ks++) {
            uint32_t a[4][4];
            uint32_t offA = rowA * (BK * 4) + ((((ks << 1) + halfA) ^ (rowA & 7)) << 4);
#pragma unroll
            for (int mf = 0; mf < 4; mf++)
                LDSM4(a[mf][0], a[mf][1], a[mf][2], a[mf][3],
                      aS + offA + mf * 16 * BK * 4);
            uint32_t b[4][2];
            uint32_t offB = rowB * (BK * 4) + ((((ks << 1) + halfB) ^ (rowB & 7)) << 4);
#pragma unroll
            for (int bf = 0; bf < 2; bf++)
                LDSM4(b[2*bf][0], b[2*bf][1], b[2*bf+1][0], b[2*bf+1][1],
                      bS + offB + bf * 16 * BK * 4);
#pragma unroll
            for (int mf = 0; mf < 4; mf++)
#pragma unroll
                for (int nf = 0; nf < 4; nf++)
                    mma_tf32(acc[mf][nf], a[mf], b[nf]);
        }
    }

    const int rbase = m0 + wm + (lane >> 2);
    const int cbase = wn + (lane & 3) * 2;

    if (MODE == 1) {
#pragma unroll
        for (int mf = 0; mf < 4; mf++)
#pragma unroll
            for (int nf = 0; nf < 4; nf++) {
                int r = rbase + mf * 16;
                int e = n0 + cbase + nf * 8;
                *reinterpret_cast<float2*>(&Cout[(size_t)r * N + e]) =
                    make_float2(acc[mf][nf][0], acc[mf][nf][1]);
                *reinterpret_cast<float2*>(&Cout[(size_t)(r + 8) * N + e]) =
                    make_float2(acc[mf][nf][2], acc[mf][nf][3]);
            }
    } else {
        float* dst; int stride; int coloff;
        if (n0 + BN <= DIN)            { dst = g_z;     stride = DIN;   coloff = n0; }
        else if (n0 + BN <= DIN+CONVD) { dst = g_xbc;   stride = CONVD; coloff = n0 - DIN; }
        else                           { dst = g_dtraw; stride = NH;    coloff = n0 - DIN - CONVD; }
#pragma unroll
        for (int mf = 0; mf < 4; mf++)
#pragma unroll
            for (int nf = 0; nf < 4; nf++) {
                int cc = cbase + nf * 8;
                if (stride == NH && cc >= NH) continue;
                int r = rbase + mf * 16;
                int e = coloff + cc;
                *reinterpret_cast<float2*>(&dst[(size_t)r * stride + e]) =
                    make_float2(acc[mf][nf][0], acc[mf][nf][1]);
                *reinterpret_cast<float2*>(&dst[(size_t)(r + 8) * stride + e]) =
                    make_float2(acc[mf][nf][2], acc[mf][nf][3]);
            }
    }
}

// ---------------- depthwise causal conv + silu (sliding window, 4 l/thread) -
__global__ __launch_bounds__(256)
void conv_kernel(const float* __restrict__ conv_w,
                 const float* __restrict__ conv_b) {
    long idx = (long)blockIdx.x * blockDim.x + threadIdx.x;
    if (idx >= (long)(BL/4) * CONVD) return;
    int c   = (int)(idx % CONVD);
    int blq = (int)(idx / CONVD);
    int lq  = blq % (SEQ/4);
    int b   = blq / (SEQ/4);
    int l0  = lq * 4;
    size_t rowbase = ((size_t)b * SEQ + l0) * CONVD + c;

    float w0 = conv_w[c*4+0], w1 = conv_w[c*4+1],
          w2 = conv_w[c*4+2], w3 = conv_w[c*4+3];
    float xm3 = 0.f, xm2 = 0.f, xm1 = 0.f;
    if (l0 > 0) {
        xm3 = g_xbc[rowbase - 3*(size_t)CONVD];
        xm2 = g_xbc[rowbase - 2*(size_t)CONVD];
        xm1 = g_xbc[rowbase - 1*(size_t)CONVD];
    }
    float x0 = g_xbc[rowbase];
    float x1 = g_xbc[rowbase + 1*(size_t)CONVD];
    float x2 = g_xbc[rowbase + 2*(size_t)CONVD];
    float x3 = g_xbc[rowbase + 3*(size_t)CONVD];
    float bias = conv_b[c];

    float a0 = bias + xm3*w0 + xm2*w1 + xm1*w2 + x0*w3;
    float a1 = bias + xm2*w0 + xm1*w1 + x0 *w2 + x1*w3;
    float a2 = bias + xm1*w0 + x0 *w1 + x1 *w2 + x2*w3;
    float a3 = bias + x0 *w0 + x1 *w1 + x2 *w2 + x3*w3;
    float v0 = silu_fast(a0);
    float v1 = silu_fast(a1);
    float v2 = silu_fast(a2);
    float v3 = silu_fast(a3);

    int bl = b * SEQ + l0;
    if (c < DIN) {
        g_x[(size_t)bl * DIN + c]         = v0;
        g_x[(size_t)(bl+1) * DIN + c]     = v1;
        g_x[(size_t)(bl+2) * DIN + c]     = v2;
        g_x[(size_t)(bl+3) * DIN + c]     = v3;
    } else if (c < DIN + DS) {
        int cc = c - DIN;
        g_Bc[(size_t)bl * DS + cc]        = v0;
        g_Bc[(size_t)(bl+1) * DS + cc]    = v1;
        g_Bc[(size_t)(bl+2) * DS + cc]    = v2;
        g_Bc[(size_t)(bl+3) * DS + cc]    = v3;
    } else {
        int cc = c - DIN - DS;
        g_Cc[(size_t)bl * DS + cc]        = v0;
        g_Cc[(size_t)(bl+1) * DS + cc]    = v1;
        g_Cc[(size_t)(bl+2) * DS + cc]    = v2;
        g_Cc[(size_t)(bl+3) * DS + cc]    = v3;
    }
}

// ---------------- softplus(dt) + per-chunk cumsum of dA ---------------------
__global__ __launch_bounds__(256)
void dtscan_kernel(const float* __restrict__ dt_bias,
                   const float* __restrict__ A_log) {
    int blk = blockIdx.x;
    int h  = blk % NH;
    int bc = blk / NH;
    int c  = bc % NC;
    int b  = bc / NC;
    int s  = threadIdx.x;
    int bl = b * SEQ + c * CHK + s;

    float xv = g_dtraw[bl * NH + h] + dt_bias[h];
    float dt = fmaxf(xv, 0.f) + log1pf(expf(-fabsf(xv)));
    g_dt[bl * NH + h] = dt;
    float A  = -expf(A_log[h]);
    float dA = dt * A;

    __shared__ float sc[CHK];
    sc[s] = dA;
    __syncthreads();
    for (int off = 1; off < CHK; off <<= 1) {
        float v = (s >= off) ? sc[s - off] : 0.f;
        __syncthreads();
        sc[s] += v;
        __syncthreads();
    }
    float cum = sc[s];
    g_ecum[blk * CHK + s] = expf(cum);
    g_r[blk * CHK + s]    = expf(dA);
    if (s == CHK - 1) g_cdecay[blk] = expf(cum);
}

// ---------------- GT[b,c,z,s] = dot(C[s], B[z]) -----------------------------
__global__ __launch_bounds__(256)
void gmat_kernel() {
    int bid = blockIdx.x;
    int bc  = bid >> 8;
    int t   = bid & 255;
    int z0  = (t >> 4) * 16;
    int s0  = (t & 15) * 16;
    int b = bc / NC, c = bc % NC;
    int blb = b * SEQ + c * CHK;
    __shared__ float Bsm[16][65];
    __shared__ float Csm[16][65];
    int tid = threadIdx.x;
#pragma unroll
    for (int t4 = 0; t4 < 4; t4++) {
        int i = tid + t4 * 256;
        int row = i >> 6, n = i & 63;
        Bsm[row][n] = g_Bc[(size_t)(blb + z0 + row) * DS + n];
        Csm[row][n] = g_Cc[(size_t)(blb + s0 + row) * DS + n];
    }
    __syncthreads();
    int zl = tid >> 4, sl = tid & 15;
    float acc = 0.f;
#pragma unroll
    for (int n = 0; n < 64; n++) acc += Csm[sl][n] * Bsm[zl][n];
    g_GT[((size_t)bc * CHK + (z0 + zl)) * CHK + (s0 + sl)] = acc;
}

// ---------------- per-chunk states[p,n] -------------------------------------
__global__ __launch_bounds__(256)
void states_kernel() {
    int blk = blockIdx.x;
    int h  = blk % NH;
    int bc = blk / NH;
    int c  = bc % NC;
    int b  = bc / NC;
    int blb = b * SEQ + c * CHK;
    int tid = threadIdx.x;

    __shared__ float coef[CHK];
    __shared__ float xs[16][128];
    __shared__ float Bsm2[16][64];

    {
        int s = tid;
        coef[s] = (s < CHK - 1) ? g_r[blk * CHK + s + 1] : 1.f;
        __syncthreads();
        for (int off = 1; off < CHK; off <<= 1) {
            float v = (s + off < CHK) ? coef[s + off] : 1.f;
            __syncthreads();
            coef[s] *= v;
            __syncthreads();
        }
        coef[s] *= g_dt[(blb + s) * NH + h];
        __syncthreads();
    }

    int n  = tid & 63;
    int pg = tid >> 6;
    float acc[32];
#pragma unroll
    for (int j = 0; j < 32; j++) acc[j] = 0.f;

    for (int s0 = 0; s0 < CHK; s0 += 16) {
#pragma unroll
        for (int t8 = 0; t8 < 8; t8++) {
            int i = tid + t8 * 256;
            int ss = i >> 7, p = i & 127;
            xs[ss][p] = g_x[(size_t)(blb + s0 + ss) * DIN + h * DH + p];
        }
#pragma unroll
        for (int t4 = 0; t4 < 4; t4++) {
            int i = tid + t4 * 256;
            int ss = i >> 6, nn = i & 63;
            Bsm2[ss][nn] = g_Bc[(size_t)(blb + s0 + ss) * DS + nn];
        }
        __syncthreads();
#pragma unroll
        for (int ss = 0; ss < 16; ss++) {
            float w = Bsm2[ss][n] * coef[s0 + ss];
            const float4* xv = reinterpret_cast<const float4*>(&xs[ss][pg * 32]);
#pragma unroll
            for (int j4 = 0; j4 < 8; j4++) {
                float4 v = xv[j4];
                acc[j4 * 4 + 0] += w * v.x;
                acc[j4 * 4 + 1] += w * v.y;
                acc[j4 * 4 + 2] += w * v.z;
                acc[j4 * 4 + 3] += w * v.w;
            }
        }
        __syncthreads();
    }
    size_t base = (size_t)blk * DH * DS;
#pragma unroll
    for (int j = 0; j < 32; j++)
        g_states[base + (size_t)(pg * 32 + j) * DS + n] = acc[j];
}

// ---------------- sequential scan over chunks (j-split, 4x parallelism) -----
__global__ __launch_bounds__(256)
void chunkscan_kernel() {
    int bid = blockIdx.x;
    int h = bid % NH, b = bid / NH;
    int j0 = blockIdx.y * 8;            // this block owns j in [j0, j0+8)
    int tid = threadIdx.x;
    float carry[8];
#pragma unroll
    for (int j = 0; j < 8; j++) carry[j] = 0.f;
    for (int c = 0; c < NC; c++) {
        int blk = (b * NC + c) * NH + h;
        size_t base = (size_t)blk * DH * DS;
        float cd = g_cdecay[blk];
#pragma unroll
        for (int j = 0; j < 8; j++) {
            size_t e = base + (size_t)(j0 + j) * 256 + tid;
            g_prev[e] = carry[j];
            carry[j] = carry[j] * cd + g_states[e];
        }
    }
}

// ---------------- Y = Y_diag + Y_off + x*D ----------------------------------
__global__ __launch_bounds__(256)
void y_kernel(const float* __restrict__ Din) {
    int blk = blockIdx.x;
    int pt  = blockIdx.y;
    int h  = blk % NH;
    int bc = blk / NH;
    int c  = bc % NC;
    int b  = bc / NC;
    int blb = b * SEQ + c * CHK;
    int p0 = pt * 32;
    int s  = threadIdx.x;

    __shared__ float rs[CHK];
    __shared__ float prevT[DS][33];
    __shared__ float xdts[64][32];

    rs[s] = g_r[blk * CHK + s];
    size_t pbase = (size_t)blk * DH * DS;
#pragma unroll
    for (int t8 = 0; t8 < 8; t8++) {
        int i = s + t8 * 256;
        int p = i >> 6, n = i & 63;
        prevT[n][p] = g_prev[pbase + (size_t)(p0 + p) * DS + n];
    }
    __syncthreads();

    float acc[32];
    float Dh = Din[h];
    {
        const float4* xv = reinterpret_cast<const float4*>(
            &g_x[(size_t)(blb + s) * DIN + h * DH + p0]);
#pragma unroll
        for (int j4 = 0; j4 < 8; j4++) {
            float4 v = xv[j4];
            acc[4 * j4 + 0] = Dh * v.x;
            acc[4 * j4 + 1] = Dh * v.y;
            acc[4 * j4 + 2] = Dh * v.z;
            acc[4 * j4 + 3] = Dh * v.w;
        }
    }
    {
        float es = g_ecum[blk * CHK + s];
        const float* Crow = &g_Cc[(size_t)(blb + s) * DS];
#pragma unroll
        for (int n = 0; n < 64; n++) {
            float cn = es * __ldg(&Crow[n]);
#pragma unroll
            for (int j = 0; j < 32; j++) acc[j] += cn * prevT[n][j];
        }
    }
    float w = 0.f;
    for (int zt = 3; zt >= 0; zt--) {
        int z0 = zt * 64;
        bool needed = (s >= z0) && ((s < z0 + 64) || (w > 0.f));
        if (__syncthreads_count(needed) == 0) continue;
#pragma unroll
        for (int t8 = 0; t8 < 8; t8++) {
            int i = s + t8 * 256;
            int zz = i >> 5, p = i & 31;
            int z = z0 + zz;
            xdts[zz][p] = g_x[(size_t)(blb + z) * DIN + h * DH + p0 + p]
                        * g_dt[(blb + z) * NH + h];
        }
        __syncthreads();
        if (z0 <= s) {
            for (int zz = 63; zz >= 0; zz--) {
                int z = z0 + zz;
                if (z > s) continue;
                if (z < s && w == 0.f) break;
                float gt = __ldg(&g_GT[((size_t)bc * CHK + z) * CHK + s]);
                if (z == s) w = 1.f;
                if (w > 0.f) {
                    float g = gt * w;
                    const float4* xv = reinterpret_cast<const float4*>(&xdts[zz][0]);
#pragma unroll
                    for (int j4 = 0; j4 < 8; j4++) {
                        float4 v = xv[j4];
                        acc[4 * j4 + 0] += g * v.x;
                        acc[4 * j4 + 1] += g * v.y;
                        acc[4 * j4 + 2] += g * v.z;
                        acc[4 * j4 + 3] += g * v.w;
                    }
                }
                w *= rs[z];
            }
        }
        __syncthreads();
    }
    float4* yo = reinterpret_cast<float4*>(
        &g_y[(size_t)(blb + s) * DIN + h * DH + p0]);
#pragma unroll
    for (int j4 = 0; j4 < 8; j4++)
        yo[j4] = make_float4(acc[4 * j4 + 0], acc[4 * j4 + 1],
                             acc[4 * j4 + 2], acc[4 * j4 + 3]);
}

// ---------------- gating + RMSNorm (output tf32-rounded for GEMM2) ----------
__global__ __launch_bounds__(256)
void norm_kernel(const float* __restrict__ norm_w) {
    int row = blockIdx.x;
    int tid = threadIdx.x;
    size_t base = (size_t)row * DIN;
    float vals[16];
    float ssum = 0.f;
#pragma unroll
    for (int j = 0; j < 16; j++) {
        int e = j * 256 + tid;
        float y = g_y[base + e];
        float z = g_z[base + e];
        float yg = y * silu_fast(z);
        vals[j] = yg;
        ssum += yg * yg;
    }
    __shared__ float red[8];
#pragma unroll
    for (int off = 16; off > 0; off >>= 1)
        ssum += __shfl_down_sync(0xffffffffu, ssum, off);
    if ((tid & 31) == 0) red[tid >> 5] = ssum;
    __syncthreads();
    if (tid == 0) {
        float t = 0.f;
#pragma unroll
        for (int i = 0; i < 8; i++) t += red[i];
        red[0] = t;
    }
    __syncthreads();
    float scale = rsqrtf(red[0] * (1.0f / DIN) + 1e-5f);
#pragma unroll
    for (int j = 0; j < 16; j++) {
        int e = j * 256 + tid;
        g_y[base + e] = rna_tf32(vals[j] * scale * norm_w[e]);
    }
}

// ---------------- launch ----------------------------------------------------
extern "C" void kernel_launch(void* const* d_in, const int* in_sizes, int n_in,
                              void* d_out, int out_size) {
    (void)in_sizes; (void)n_in; (void)out_size;
    const float* u       = (const float*)d_in[0];
    const float* W_in    = (const float*)d_in[1];
    const float* conv_w  = (const float*)d_in[2];
    const float* conv_b  = (const float*)d_in[3];
    const float* dt_bias = (const float*)d_in[4];
    const float* A_log   = (const float*)d_in[5];
    const float* Dp      = (const float*)d_in[6];
    const float* norm_w  = (const float*)d_in[7];
    const float* W_out   = (const float*)d_in[8];
    float* out = (float*)d_out;

    void *uP, *WinP, *WoutP, *yP;
    cudaGetSymbolAddress(&uP, g_u);
    cudaGetSymbolAddress(&WinP, g_Win);
    cudaGetSymbolAddress(&WoutP, g_Wout);
    cudaGetSymbolAddress(&yP, g_y);

    cudaFuncSetAttribute(gemm_mma<0>, cudaFuncAttributeMaxDynamicSharedMemorySize,
                         GSMEM_BYTES);
    cudaFuncSetAttribute(gemm_mma<1>, cudaFuncAttributeMaxDynamicSharedMemorySize,
                         GSMEM_BYTES);

    // merged tf32 rna prep for u / W_in / W_out
    int n4all = N4_U + N4_WIN + N4_WOUT;
    prep_round_all<<<(n4all + 255) / 256, 256>>>(u, W_in, W_out);

    // in-projection: [BL, DPROJ] = u @ W_in^T
    dim3 g1((DPROJ + BN - 1) / BN, BL / BM);     // 66 x 64
    gemm_mma<0><<<g1, 256, GSMEM_BYTES>>>((const float*)uP, (const float*)WinP,
                                          nullptr, DPROJ, DM);

    long total = (long)(BL/4) * CONVD;
    conv_kernel<<<(unsigned)((total + 255) / 256), 256>>>(conv_w, conv_b);

    dtscan_kernel<<<BATCH * NC * NH, 256>>>(dt_bias, A_log);
    gmat_kernel<<<BATCH * NC * 256, 256>>>();
    states_kernel<<<BATCH * NC * NH, 256>>>();

    dim3 gc(BATCH * NH, 4);
    chunkscan_kernel<<<gc, 256>>>();

    dim3 gy(BATCH * NC * NH, 4);
    y_kernel<<<gy, 256>>>(Dp);

    norm_kernel<<<BL, 256>>>(norm_w);

    // out-projection: [BL, DM] = yn @ W_out^T
    dim3 g2(DM / BN, BL / BM);                   // 16 x 64
    gemm_mma<1><<<g2, 256, GSMEM_BYTES>>>((const float*)yP, (const float*)WoutP,
                                          out, DM, DIN);
}